// round 13
// baseline (speedup 1.0000x reference)
#include <cuda_runtime.h>
#include <cuda_fp16.h>
#include <stdint.h>

#define N_NODES 20000
#define D_IN    128
#define D_H     256
#define D_H2    128               // half2 columns
#define LN_EPS  1e-5f
#define MAX_E   330000
#define NB_SCAN ((N_NODES + 255) / 256)   // 79

// ---------------- scratch (no dynamic allocation allowed) ----------------
// invariant: g_deg == 0 and g_cnt == 0 at kernel_launch entry
// (zero-initialized statics; scan1 restores after reading)
__device__ float  g_deg [N_NODES];
__device__ int    g_cnt [N_NODES];
__device__ float  g_dinv[N_NODES];
__device__ int    g_off [N_NODES + 1];
__device__ int    g_cur [N_NODES];        // fill cursor (re-init by scan2)
__device__ int    g_blksum[NB_SCAN];
__device__ int    g_csr_src[MAX_E];
__device__ float  g_csr_nrm[MAX_E];
__device__ __half g_h1h [N_NODES * D_H];  // x@W1 (fp16), later h@W2 (fp16)
__device__ float  g_hres[N_NODES * D_H];  // x@Wres + bres (fp32)
__device__ __half g_hh  [N_NODES * D_H];  // h after LN1 (fp16)

// ---------------- helpers ----------------
__device__ __forceinline__ uint32_t pack_h2(float a, float b) {
    __half2 h = __floats2half2_rn(a, b);
    return *reinterpret_cast<uint32_t*>(&h);
}

__device__ __forceinline__ void mma_f16(float* c, const uint32_t* a, const uint32_t* b) {
    asm volatile(
        "mma.sync.aligned.m16n8k16.row.col.f32.f16.f16.f32 "
        "{%0,%1,%2,%3}, {%4,%5,%6,%7}, {%8,%9}, {%0,%1,%2,%3};"
        : "+f"(c[0]), "+f"(c[1]), "+f"(c[2]), "+f"(c[3])
        : "r"(a[0]), "r"(a[1]), "r"(a[2]), "r"(a[3]), "r"(b[0]), "r"(b[1]));
}

// ---------------- degree + count accumulation over edges ----------------
__global__ void degcnt_kernel(const int* __restrict__ dst,
                              const float* __restrict__ w, int E) {
    for (int e = blockIdx.x * blockDim.x + threadIdx.x; e < E;
         e += gridDim.x * blockDim.x) {
        int d = dst[e];
        atomicAdd(&g_deg[d], w[e]);
        atomicAdd(&g_cnt[d], 1);
    }
}

// ---------------- scan pass 1: per-block exclusive scan + dinv --------------
// also RESETS g_cnt/g_deg to restore the entry invariant for the next replay.
__global__ void scan1_kernel() {
    const int t = threadIdx.x, b = blockIdx.x;
    const int i = b * 256 + t;
    const int lane = t & 31, wid = t >> 5;

    int v = 0;
    if (i < N_NODES) {
        v = g_cnt[i];
        g_cnt[i] = 0;                         // restore invariant
        float d = g_deg[i];
        g_deg[i] = 0.0f;                      // restore invariant
        g_dinv[i] = rsqrtf(d + 1.0f);         // + self-loop weight 1
    }

    int s = v;
#pragma unroll
    for (int o = 1; o < 32; o <<= 1) {
        int u = __shfl_up_sync(0xFFFFFFFFu, s, o);
        if (lane >= o) s += u;
    }
    __shared__ int wsum[8];
    if (lane == 31) wsum[wid] = s;
    __syncthreads();
    int base = 0;
#pragma unroll
    for (int w = 0; w < 8; w++) base += (w < wid) ? wsum[w] : 0;
    if (i < N_NODES) g_off[i] = base + s - v;
    if (t == 255) g_blksum[b] = base + s;
}

// ---------------- scan pass 2: add block bases, init fill cursor ------------
__global__ void scan2_kernel(int E) {
    const int t = threadIdx.x, b = blockIdx.x;
    __shared__ int sbase;
    if (t < 32) {
        int acc = 0;
        for (int j = t; j < b; j += 32) acc += g_blksum[j];
#pragma unroll
        for (int o = 16; o; o >>= 1) acc += __shfl_xor_sync(0xFFFFFFFFu, acc, o);
        if (t == 0) sbase = acc;
    }
    __syncthreads();
    const int i = b * 256 + t;
    if (i < N_NODES) {
        int off = g_off[i] + sbase;
        g_off[i] = off;
        g_cur[i] = off;                        // fill cursor
    }
    if (b == 0 && t == 0) g_off[N_NODES] = E;
}

// ---------------- CSR fill (also precomputes edge norm) ----------------
__global__ void fill_kernel(const int* __restrict__ src,
                            const int* __restrict__ dst,
                            const float* __restrict__ w, int E) {
    for (int e = blockIdx.x * blockDim.x + threadIdx.x; e < E;
         e += gridDim.x * blockDim.x) {
        int s = src[e];
        int d = dst[e];
        int pos = atomicAdd(&g_cur[d], 1);
        g_csr_src[pos] = s;
        g_csr_nrm[pos] = g_dinv[s] * w[e] * g_dinv[d];
    }
}

// ---------------- FP16 tensor-core GEMM (single-buffer, R11 structure) ------
// C[M,256] = A[M,K] @ B[K,256] (+bias). BM=128 BN=128 BK=16, 256 thr (8 warps).
// A dtype templated: float (converted at STS) or __half (direct uint4 copy).
template<int K, typename AT>
__global__ __launch_bounds__(256)
void f16_gemm_kernel(const AT* __restrict__ A, int M, int nb,
                     const float* __restrict__ Bm1, const float* __restrict__ bias1,
                     __half* __restrict__ C1h, float* __restrict__ C1f,
                     const float* __restrict__ Bm2, const float* __restrict__ bias2,
                     __half* __restrict__ C2h, float* __restrict__ C2f) {
    __shared__ uint32_t As2[128][12];
    __shared__ uint32_t Bs2[8][136];

    const int tid  = threadIdx.x;
    const int lane = tid & 31;
    const int wid  = tid >> 5;
    const int wm   = (wid & 1) * 64;
    const int wn   = (wid >> 1) * 32;
    const int g    = lane >> 2;
    const int tg   = lane & 3;

    const int bm  = blockIdx.x * 128;
    const int mat = blockIdx.y / nb;
    const int bn  = (blockIdx.y % nb) * 128;

    const float* Bw   = mat ? Bm2   : Bm1;
    const float* bias = mat ? bias2 : bias1;
    __half*      Ch   = mat ? C2h   : C1h;
    float*       Cf   = mat ? C2f   : C1f;

    const int a_row = tid >> 1;          // 0..127
    const int a_k   = (tid & 1) * 8;     // element offset
    const int a_k2  = (tid & 1) * 4;     // uint32 offset
    const int b_r   = tid >> 5;          // 0..7
    const int b_c   = (tid & 31) * 4;    // 0..124
    const bool a_ok = (bm + a_row) < M;
    const long a_base = (long)(bm + a_row) * K;

    float acc[4][4][4];
#pragma unroll
    for (int mt = 0; mt < 4; mt++)
#pragma unroll
        for (int nt = 0; nt < 4; nt++)
#pragma unroll
            for (int i = 0; i < 4; i++) acc[mt][nt][i] = 0.0f;

    float4 av0, av1;
    uint4  avh;
    float4 bv0, bv1;

    auto load_g = [&](int kt) {
        if (sizeof(AT) == 2) {
            avh = make_uint4(0u, 0u, 0u, 0u);
            if (a_ok)
                avh = *reinterpret_cast<const uint4*>(
                    reinterpret_cast<const __half*>(A) + a_base + kt + a_k);
        } else {
            av0 = make_float4(0.f,0.f,0.f,0.f); av1 = av0;
            if (a_ok) {
                const float* Af = reinterpret_cast<const float*>(A);
                av0 = *reinterpret_cast<const float4*>(Af + a_base + kt + a_k);
                av1 = *reinterpret_cast<const float4*>(Af + a_base + kt + a_k + 4);
            }
        }
        bv0 = *reinterpret_cast<const float4*>(Bw + (long)(kt + 2 * b_r)     * D_H + bn + b_c);
        bv1 = *reinterpret_cast<const float4*>(Bw + (long)(kt + 2 * b_r + 1) * D_H + bn + b_c);
    };

    auto store_s = [&]() {
        uint4 pa;
        if (sizeof(AT) == 2) {
            pa = avh;
        } else {
            pa = make_uint4(pack_h2(av0.x, av0.y), pack_h2(av0.z, av0.w),
                            pack_h2(av1.x, av1.y), pack_h2(av1.z, av1.w));
        }
        *reinterpret_cast<uint4*>(&As2[a_row][a_k2]) = pa;
        uint4 pb = make_uint4(pack_h2(bv0.x, bv1.x), pack_h2(bv0.y, bv1.y),
                              pack_h2(bv0.z, bv1.z), pack_h2(bv0.w, bv1.w));
        *reinterpret_cast<uint4*>(&Bs2[b_r][b_c]) = pb;
    };

    const int T = K / 16;
    load_g(0);
    for (int t = 0; t < T; t++) {
        __syncthreads();
        store_s();
        __syncthreads();

        if (t + 1 < T) load_g((t + 1) * 16);   // prefetch overlaps mma block

        uint32_t af[4][4], bf[4][2];
#pragma unroll
        for (int mt = 0; mt < 4; mt++) {
            int r0 = wm + mt * 16 + g;
            af[mt][0] = As2[r0    ][tg    ];
            af[mt][1] = As2[r0 + 8][tg    ];
            af[mt][2] = As2[r0    ][tg + 4];
            af[mt][3] = As2[r0 + 8][tg + 4];
        }
#pragma unroll
        for (int nt = 0; nt < 4; nt++) {
            int c0 = wn + nt * 8 + g;
            bf[nt][0] = Bs2[tg    ][c0];
            bf[nt][1] = Bs2[tg + 4][c0];
        }
#pragma unroll
        for (int mt = 0; mt < 4; mt++)
#pragma unroll
            for (int nt = 0; nt < 4; nt++)
                mma_f16(acc[mt][nt], af[mt], bf[nt]);
    }

#pragma unroll
    for (int mt = 0; mt < 4; mt++) {
        int row = bm + wm + mt * 16 + g;
#pragma unroll
        for (int nt = 0; nt < 4; nt++) {
            int col = bn + wn + nt * 8 + tg * 2;
            float b0 = bias ? bias[col]     : 0.0f;
            float b1 = bias ? bias[col + 1] : 0.0f;
            float v00 = acc[mt][nt][0] + b0, v01 = acc[mt][nt][1] + b1;
            float v10 = acc[mt][nt][2] + b0, v11 = acc[mt][nt][3] + b1;
            if (Ch) {
                if (row < M)
                    *reinterpret_cast<__half2*>(Ch + (long)row * D_H + col) =
                        __floats2half2_rn(v00, v01);
                if (row + 8 < M)
                    *reinterpret_cast<__half2*>(Ch + (long)(row + 8) * D_H + col) =
                        __floats2half2_rn(v10, v11);
            } else {
                if (row < M)
                    *reinterpret_cast<float2*>(Cf + (long)row * D_H + col) =
                        make_float2(v00, v01);
                if (row + 8 < M)
                    *reinterpret_cast<float2*>(Cf + (long)(row + 8) * D_H + col) =
                        make_float2(v10, v11);
            }
        }
    }
}

// ---------------- fused CSR gather (half2, split-edge) + ReLU? + res + LN ---
template<bool RELU, typename RT, typename OT>
__global__ __launch_bounds__(256)
void gather_ln_kernel(const __half* __restrict__ feat,
                      const RT* __restrict__ resid,
                      const float* __restrict__ bias,
                      const float* __restrict__ gamma,
                      const float* __restrict__ beta,
                      OT* __restrict__ out) {
    const int row = blockIdx.x;
    const int tid = threadIdx.x;
    const int c2  = tid & 127;        // half2 column
    const int par = tid >> 7;         // edge parity 0/1
    const __half2* f2 = reinterpret_cast<const __half2*>(feat);
    const long idx2 = (long)row * D_H2 + c2;

    __shared__ int    s_src[64];
    __shared__ float  s_nrm[64];
    __shared__ float2 s_par[128];

    const int beg = g_off[row];
    const int end = g_off[row + 1];
    const float di = g_dinv[row];

    float2 a0 = make_float2(0.f, 0.f), a1 = a0, a2 = a0, a3 = a0;
    if (par == 0) {   // self-loop
        float2 v = __half22float2(f2[idx2]);
        a0.x = di * di * v.x;
        a0.y = di * di * v.y;
    }

    for (int chunk = beg; chunk < end; chunk += 64) {
        int n = min(64, end - chunk);
        if (chunk != beg) __syncthreads();
        if (tid < n) {
            s_src[tid] = g_csr_src[chunk + tid];
            s_nrm[tid] = g_csr_nrm[chunk + tid];
        }
        __syncthreads();
        int k = par;
        for (; k + 6 < n; k += 8) {
            float2 v0 = __half22float2(f2[(long)s_src[k    ] * D_H2 + c2]);
            float2 v1 = __half22float2(f2[(long)s_src[k + 2] * D_H2 + c2]);
            float2 v2 = __half22float2(f2[(long)s_src[k + 4] * D_H2 + c2]);
            float2 v3 = __half22float2(f2[(long)s_src[k + 6] * D_H2 + c2]);
            float n0 = s_nrm[k], n1 = s_nrm[k + 2], n2 = s_nrm[k + 4], n3 = s_nrm[k + 6];
            a0.x += n0 * v0.x; a0.y += n0 * v0.y;
            a1.x += n1 * v1.x; a1.y += n1 * v1.y;
            a2.x += n2 * v2.x; a2.y += n2 * v2.y;
            a3.x += n3 * v3.x; a3.y += n3 * v3.y;
        }
        for (; k < n; k += 2) {
            float2 v = __half22float2(f2[(long)s_src[k] * D_H2 + c2]);
            float nn = s_nrm[k];
            a0.x += nn * v.x; a0.y += nn * v.y;
        }
    }

    float2 acc = make_float2((a0.x + a1.x) + (a2.x + a3.x),
                             (a0.y + a1.y) + (a2.y + a3.y));

    // combine the two parity groups
    __syncthreads();
    if (par == 1) s_par[c2] = acc;
    __syncthreads();

    float2 t2 = make_float2(0.f, 0.f);
    if (par == 0) {
        float2 o = s_par[c2];
        acc.x += o.x; acc.y += o.y;
        int col = c2 * 2;
        float bx = bias[col], by = bias[col + 1];
        float2 r;
        if (sizeof(RT) == 2) {
            r = __half22float2(
                reinterpret_cast<const __half2*>(resid)[(long)row * D_H2 + c2]);
        } else {
            r = *reinterpret_cast<const float2*>(
                reinterpret_cast<const float*>(resid) + (long)row * D_H + col);
        }
        if (RELU) {
            t2.x = r.x + fmaxf(acc.x + bx, 0.0f);
            t2.y = r.y + fmaxf(acc.y + by, 0.0f);
        } else {
            t2.x = r.x + acc.x + bx;
            t2.y = r.y + acc.y + by;
        }
    }

    // LN stats over 256 values (par-1 threads contribute 0)
    float s = t2.x + t2.y, sq = t2.x * t2.x + t2.y * t2.y;
#pragma unroll
    for (int o = 16; o; o >>= 1) {
        s  += __shfl_xor_sync(0xFFFFFFFFu, s, o);
        sq += __shfl_xor_sync(0xFFFFFFFFu, sq, o);
    }
    __shared__ float ss[8], ssq[8];
    int wid = tid >> 5;
    if ((tid & 31) == 0) { ss[wid] = s; ssq[wid] = sq; }
    __syncthreads();
    float ts = 0.f, tq = 0.f;
#pragma unroll
    for (int i = 0; i < 8; i++) { ts += ss[i]; tq += ssq[i]; }
    float mu  = ts * (1.0f / D_H);
    float var = tq * (1.0f / D_H) - mu * mu;

    if (par == 0) {
        float rstd = rsqrtf(var + LN_EPS);
        int col = c2 * 2;
        float ox = (t2.x - mu) * rstd * gamma[col]     + beta[col];
        float oy = (t2.y - mu) * rstd * gamma[col + 1] + beta[col + 1];
        if (sizeof(OT) == 2) {
            reinterpret_cast<__half2*>(out)[(long)row * D_H2 + c2] =
                __floats2half2_rn(ox, oy);
        } else {
            *reinterpret_cast<float2*>(
                reinterpret_cast<float*>(out) + (long)row * D_H + col) =
                make_float2(ox, oy);
        }
    }
}

// ---------------- launch ----------------
extern "C" void kernel_launch(void* const* d_in, const int* in_sizes, int n_in,
                              void* d_out, int out_size) {
    const float* x      = (const float*)d_in[0];
    const int*   ei     = (const int*)d_in[1];     // [2,E] int32
    const float* ew     = (const float*)d_in[2];
    const float* W1     = (const float*)d_in[3];
    const float* b1     = (const float*)d_in[4];
    const float* W2     = (const float*)d_in[5];
    const float* b2     = (const float*)d_in[6];
    const float* Wres   = (const float*)d_in[7];
    const float* bres   = (const float*)d_in[8];
    const float* gamma1 = (const float*)d_in[9];
    const float* beta1  = (const float*)d_in[10];
    const float* gamma2 = (const float*)d_in[11];
    const float* beta2  = (const float*)d_in[12];
    float* out = (float*)d_out;

    const int E = in_sizes[2];
    const int* src = ei;
    const int* dst = ei + E;

    __half *p_h1h = nullptr, *p_hh = nullptr;
    float *p_hres = nullptr;
    cudaGetSymbolAddress((void**)&p_h1h,  g_h1h);
    cudaGetSymbolAddress((void**)&p_hres, g_hres);
    cudaGetSymbolAddress((void**)&p_hh,   g_hh);

    // lazily-created side stream + events (host resources only)
    static cudaStream_t sideStream = nullptr;
    static cudaEvent_t  evFork = nullptr, evJoin = nullptr;
    if (!sideStream) {
        if (cudaStreamCreateWithFlags(&sideStream, cudaStreamNonBlocking) != cudaSuccess)
            sideStream = nullptr;
        if (sideStream) {
            cudaEventCreateWithFlags(&evFork, cudaEventDisableTiming);
            cudaEventCreateWithFlags(&evJoin, cudaEventDisableTiming);
        }
    }
    cudaStream_t cs = sideStream ? sideStream : (cudaStream_t)0;

    // fork: CSR build chain on side stream (4 kernels; init eliminated via
    // the scan1 reset invariant)
    if (sideStream) {
        cudaEventRecord(evFork, 0);
        cudaStreamWaitEvent(sideStream, evFork, 0);
    }
    degcnt_kernel<<<(E + 255) / 256, 256, 0, cs>>>(dst, ew, E);
    scan1_kernel<<<NB_SCAN, 256, 0, cs>>>();
    scan2_kernel<<<NB_SCAN, 256, 0, cs>>>(E);
    fill_kernel<<<(E + 255) / 256, 256, 0, cs>>>(src, dst, ew, E);
    if (sideStream) cudaEventRecord(evJoin, sideStream);

    const int mblk = (N_NODES + 127) / 128;   // 157
    const int nb = D_H / 128;                 // 2 col-blocks per matrix

    // main stream (concurrent with CSR build):
    // h1(fp16) = x@W1 ; hres(fp32) = x@Wres + bres
    f16_gemm_kernel<D_IN, float><<<dim3(mblk, 2 * nb), 256>>>(
        x, N_NODES, nb,
        W1, nullptr, p_h1h, nullptr,
        Wres, bres, nullptr, p_hres);

    // join: gather needs both CSR and GEMM results
    if (sideStream) cudaStreamWaitEvent((cudaStream_t)0, evJoin, 0);

    // hop 0: gather(h1) + b1 + relu + hres residual + LN -> h (fp16)
    gather_ln_kernel<true, float, __half><<<N_NODES, 256>>>(
        p_h1h, p_hres, b1, gamma1, beta1, p_hh);

    // h2(fp16) = h(fp16) @ W2
    f16_gemm_kernel<D_H, __half><<<dim3(mblk, nb), 256>>>(
        p_hh, N_NODES, nb,
        W2, nullptr, p_h1h, nullptr,
        W2, nullptr, p_h1h, nullptr);

    // hop 1: gather(h2) + b2 + h residual(fp16) + LN -> out (fp32)
    gather_ln_kernel<false, __half, float><<<N_NODES, 256>>>(
        p_h1h, p_hh, b2, gamma2, beta2, out);
}

// round 14
// speedup vs baseline: 1.0720x; 1.0720x over previous
#include <cuda_runtime.h>
#include <cuda_fp16.h>
#include <stdint.h>

#define N_NODES 20000
#define D_IN    128
#define D_H     256
#define D_H2    128               // half2 columns
#define LN_EPS  1e-5f
#define MAX_E   330000
#define NB_SCAN ((N_NODES + 255) / 256)   // 79
#define DEG_SCALE 1048576.0f              // 2^20 fixed-point for edge weights

// ---------------- scratch (no dynamic allocation allowed) ----------------
// invariant: g_degcnt == 0 at kernel_launch entry (zeroed statics; scan1
// restores after reading)
__device__ unsigned long long g_degcnt[N_NODES];  // cnt<<40 | deg_fp20
__device__ float  g_dinv[N_NODES];
__device__ int    g_off [N_NODES + 1];
__device__ int    g_cur [N_NODES];        // fill cursor (re-init by scan2)
__device__ int    g_blksum[NB_SCAN];
__device__ int2   g_csr [MAX_E];          // {src, nrm-as-int}
__device__ __half g_h1h [N_NODES * D_H];  // x@W1 (fp16), later h@W2 (fp16)
__device__ float  g_hres[N_NODES * D_H];  // x@Wres + bres (fp32)
__device__ float  g_h   [N_NODES * D_H];  // after LN1 (fp32)

// ---------------- helpers ----------------
__device__ __forceinline__ uint32_t pack_h2(float a, float b) {
    __half2 h = __floats2half2_rn(a, b);
    return *reinterpret_cast<uint32_t*>(&h);
}

__device__ __forceinline__ void mma_f16(float* c, const uint32_t* a, const uint32_t* b) {
    asm volatile(
        "mma.sync.aligned.m16n8k16.row.col.f32.f16.f16.f32 "
        "{%0,%1,%2,%3}, {%4,%5,%6,%7}, {%8,%9}, {%0,%1,%2,%3};"
        : "+f"(c[0]), "+f"(c[1]), "+f"(c[2]), "+f"(c[3])
        : "r"(a[0]), "r"(a[1]), "r"(a[2]), "r"(a[3]), "r"(b[0]), "r"(b[1]));
}

// ---------------- degree + count via ONE packed 64-bit atomic ---------------
__global__ void degcnt_kernel(const int* __restrict__ dst,
                              const float* __restrict__ w, int E) {
    for (int e = blockIdx.x * blockDim.x + threadIdx.x; e < E;
         e += gridDim.x * blockDim.x) {
        int d = dst[e];
        unsigned long long packed =
            (1ULL << 40) | (unsigned long long)__float2uint_rn(w[e] * DEG_SCALE);
        atomicAdd(&g_degcnt[d], packed);
    }
}

// ---------------- scan pass 1: per-block exclusive scan + dinv --------------
// also RESETS g_degcnt to restore the entry invariant for the next replay.
__global__ void scan1_kernel() {
    const int t = threadIdx.x, b = blockIdx.x;
    const int i = b * 256 + t;
    const int lane = t & 31, wid = t >> 5;

    int v = 0;
    if (i < N_NODES) {
        unsigned long long pc = g_degcnt[i];
        g_degcnt[i] = 0ULL;                               // restore invariant
        v = (int)(pc >> 40);
        float d = (float)(pc & 0xFFFFFFFFFFULL) * (1.0f / DEG_SCALE);
        g_dinv[i] = rsqrtf(d + 1.0f);                     // + self-loop
    }

    int s = v;
#pragma unroll
    for (int o = 1; o < 32; o <<= 1) {
        int u = __shfl_up_sync(0xFFFFFFFFu, s, o);
        if (lane >= o) s += u;
    }
    __shared__ int wsum[8];
    if (lane == 31) wsum[wid] = s;
    __syncthreads();
    int base = 0;
#pragma unroll
    for (int w = 0; w < 8; w++) base += (w < wid) ? wsum[w] : 0;
    if (i < N_NODES) g_off[i] = base + s - v;
    if (t == 255) g_blksum[b] = base + s;
}

// ---------------- scan pass 2: add block bases, init fill cursor ------------
__global__ void scan2_kernel(int E) {
    const int t = threadIdx.x, b = blockIdx.x;
    __shared__ int sbase;
    if (t < 32) {
        int acc = 0;
        for (int j = t; j < b; j += 32) acc += g_blksum[j];
#pragma unroll
        for (int o = 16; o; o >>= 1) acc += __shfl_xor_sync(0xFFFFFFFFu, acc, o);
        if (t == 0) sbase = acc;
    }
    __syncthreads();
    const int i = b * 256 + t;
    if (i < N_NODES) {
        int off = g_off[i] + sbase;
        g_off[i] = off;
        g_cur[i] = off;
    }
    if (b == 0 && t == 0) g_off[N_NODES] = E;
}

// ---------------- CSR fill: ONE 8-byte store per edge ----------------
__global__ void fill_kernel(const int* __restrict__ src,
                            const int* __restrict__ dst,
                            const float* __restrict__ w, int E) {
    for (int e = blockIdx.x * blockDim.x + threadIdx.x; e < E;
         e += gridDim.x * blockDim.x) {
        int s = src[e];
        int d = dst[e];
        int pos = atomicAdd(&g_cur[d], 1);
        float nrm = g_dinv[s] * w[e] * g_dinv[d];
        g_csr[pos] = make_int2(s, __float_as_int(nrm));
    }
}

// ---------------- FP16 tensor-core GEMM (R11 structure, float A) ------------
// C[M,256] = A[M,K] @ B[K,256] (+bias). BM=128 BN=128 BK=16, 256 thr (8 warps).
template<int K>
__global__ __launch_bounds__(256)
void f16_gemm_kernel(const float* __restrict__ A, int M, int nb,
                     const float* __restrict__ Bm1, const float* __restrict__ bias1,
                     __half* __restrict__ C1h, float* __restrict__ C1f,
                     const float* __restrict__ Bm2, const float* __restrict__ bias2,
                     __half* __restrict__ C2h, float* __restrict__ C2f) {
    __shared__ uint32_t As2[128][12];
    __shared__ uint32_t Bs2[8][136];

    const int tid  = threadIdx.x;
    const int lane = tid & 31;
    const int wid  = tid >> 5;
    const int wm   = (wid & 1) * 64;
    const int wn   = (wid >> 1) * 32;
    const int g    = lane >> 2;
    const int tg   = lane & 3;

    const int bm  = blockIdx.x * 128;
    const int mat = blockIdx.y / nb;
    const int bn  = (blockIdx.y % nb) * 128;

    const float* Bw   = mat ? Bm2   : Bm1;
    const float* bias = mat ? bias2 : bias1;
    __half*      Ch   = mat ? C2h   : C1h;
    float*       Cf   = mat ? C2f   : C1f;

    const int a_row = tid >> 1;
    const int a_k   = (tid & 1) * 8;
    const int a_k2  = (tid & 1) * 4;
    const int b_r   = tid >> 5;
    const int b_c   = (tid & 31) * 4;
    const bool a_ok = (bm + a_row) < M;
    const long a_base = (long)(bm + a_row) * K;

    float acc[4][4][4];
#pragma unroll
    for (int mt = 0; mt < 4; mt++)
#pragma unroll
        for (int nt = 0; nt < 4; nt++)
#pragma unroll
            for (int i = 0; i < 4; i++) acc[mt][nt][i] = 0.0f;

    float4 av0 = make_float4(0.f,0.f,0.f,0.f), av1 = av0;
    if (a_ok) {
        av0 = *reinterpret_cast<const float4*>(A + a_base + a_k);
        av1 = *reinterpret_cast<const float4*>(A + a_base + a_k + 4);
    }
    float4 bv0 = *reinterpret_cast<const float4*>(Bw + (long)(2 * b_r)     * D_H + bn + b_c);
    float4 bv1 = *reinterpret_cast<const float4*>(Bw + (long)(2 * b_r + 1) * D_H + bn + b_c);

    const int T = K / 16;
    for (int t = 0; t < T; t++) {
        __syncthreads();
        {
            uint4 pa = make_uint4(pack_h2(av0.x, av0.y), pack_h2(av0.z, av0.w),
                                  pack_h2(av1.x, av1.y), pack_h2(av1.z, av1.w));
            *reinterpret_cast<uint4*>(&As2[a_row][a_k2]) = pa;
            uint4 pb = make_uint4(pack_h2(bv0.x, bv1.x), pack_h2(bv0.y, bv1.y),
                                  pack_h2(bv0.z, bv1.z), pack_h2(bv0.w, bv1.w));
            *reinterpret_cast<uint4*>(&Bs2[b_r][b_c]) = pb;
        }
        __syncthreads();

        if (t + 1 < T) {
            int kt = (t + 1) * 16;
            av0 = make_float4(0.f,0.f,0.f,0.f); av1 = av0;
            if (a_ok) {
                av0 = *reinterpret_cast<const float4*>(A + a_base + kt + a_k);
                av1 = *reinterpret_cast<const float4*>(A + a_base + kt + a_k + 4);
            }
            bv0 = *reinterpret_cast<const float4*>(Bw + (long)(kt + 2 * b_r)     * D_H + bn + b_c);
            bv1 = *reinterpret_cast<const float4*>(Bw + (long)(kt + 2 * b_r + 1) * D_H + bn + b_c);
        }

        uint32_t af[4][4], bf[4][2];
#pragma unroll
        for (int mt = 0; mt < 4; mt++) {
            int r0 = wm + mt * 16 + g;
            af[mt][0] = As2[r0    ][tg    ];
            af[mt][1] = As2[r0 + 8][tg    ];
            af[mt][2] = As2[r0    ][tg + 4];
            af[mt][3] = As2[r0 + 8][tg + 4];
        }
#pragma unroll
        for (int nt = 0; nt < 4; nt++) {
            int c0 = wn + nt * 8 + g;
            bf[nt][0] = Bs2[tg    ][c0];
            bf[nt][1] = Bs2[tg + 4][c0];
        }
#pragma unroll
        for (int mt = 0; mt < 4; mt++)
#pragma unroll
            for (int nt = 0; nt < 4; nt++)
                mma_f16(acc[mt][nt], af[mt], bf[nt]);
    }

#pragma unroll
    for (int mt = 0; mt < 4; mt++) {
        int row = bm + wm + mt * 16 + g;
#pragma unroll
        for (int nt = 0; nt < 4; nt++) {
            int col = bn + wn + nt * 8 + tg * 2;
            float b0 = bias ? bias[col]     : 0.0f;
            float b1 = bias ? bias[col + 1] : 0.0f;
            float v00 = acc[mt][nt][0] + b0, v01 = acc[mt][nt][1] + b1;
            float v10 = acc[mt][nt][2] + b0, v11 = acc[mt][nt][3] + b1;
            if (Ch) {
                if (row < M)
                    *reinterpret_cast<__half2*>(Ch + (long)row * D_H + col) =
                        __floats2half2_rn(v00, v01);
                if (row + 8 < M)
                    *reinterpret_cast<__half2*>(Ch + (long)(row + 8) * D_H + col) =
                        __floats2half2_rn(v10, v11);
            } else {
                if (row < M)
                    *reinterpret_cast<float2*>(Cf + (long)row * D_H + col) =
                        make_float2(v00, v01);
                if (row + 8 < M)
                    *reinterpret_cast<float2*>(Cf + (long)(row + 8) * D_H + col) =
                        make_float2(v10, v11);
            }
        }
    }
}

// ---------------- fused CSR gather (half2, split-edge) + ReLU? + res + LN ---
// R11 structure; edge meta now a single int2 stream.
template<bool RELU>
__global__ __launch_bounds__(256)
void gather_ln_kernel(const __half* __restrict__ feat,
                      const float* __restrict__ resid,
                      const float* __restrict__ bias,
                      const float* __restrict__ gamma,
                      const float* __restrict__ beta,
                      float* __restrict__ out) {
    const int row = blockIdx.x;
    const int tid = threadIdx.x;
    const int c2  = tid & 127;
    const int par = tid >> 7;
    const __half2* f2 = reinterpret_cast<const __half2*>(feat);
    const long idx2 = (long)row * D_H2 + c2;

    __shared__ int2   s_meta[64];
    __shared__ float2 s_par[128];

    const int beg = g_off[row];
    const int end = g_off[row + 1];
    const float di = g_dinv[row];

    float2 a0 = make_float2(0.f, 0.f), a1 = a0, a2 = a0, a3 = a0;
    if (par == 0) {   // self-loop
        float2 v = __half22float2(f2[idx2]);
        a0.x = di * di * v.x;
        a0.y = di * di * v.y;
    }

    for (int chunk = beg; chunk < end; chunk += 64) {
        int n = min(64, end - chunk);
        if (chunk != beg) __syncthreads();
        if (tid < n) s_meta[tid] = g_csr[chunk + tid];
        __syncthreads();
        int k = par;
        for (; k + 6 < n; k += 8) {
            int2 m0 = s_meta[k], m1 = s_meta[k + 2], m2 = s_meta[k + 4], m3 = s_meta[k + 6];
            float2 v0 = __half22float2(f2[(long)m0.x * D_H2 + c2]);
            float2 v1 = __half22float2(f2[(long)m1.x * D_H2 + c2]);
            float2 v2 = __half22float2(f2[(long)m2.x * D_H2 + c2]);
            float2 v3 = __half22float2(f2[(long)m3.x * D_H2 + c2]);
            float n0 = __int_as_float(m0.y), n1 = __int_as_float(m1.y);
            float n2 = __int_as_float(m2.y), n3 = __int_as_float(m3.y);
            a0.x += n0 * v0.x; a0.y += n0 * v0.y;
            a1.x += n1 * v1.x; a1.y += n1 * v1.y;
            a2.x += n2 * v2.x; a2.y += n2 * v2.y;
            a3.x += n3 * v3.x; a3.y += n3 * v3.y;
        }
        for (; k < n; k += 2) {
            int2 m = s_meta[k];
            float2 v = __half22float2(f2[(long)m.x * D_H2 + c2]);
            float nn = __int_as_float(m.y);
            a0.x += nn * v.x; a0.y += nn * v.y;
        }
    }

    float2 acc = make_float2((a0.x + a1.x) + (a2.x + a3.x),
                             (a0.y + a1.y) + (a2.y + a3.y));

    __syncthreads();
    if (par == 1) s_par[c2] = acc;
    __syncthreads();

    float2 t2 = make_float2(0.f, 0.f);
    if (par == 0) {
        float2 o = s_par[c2];
        acc.x += o.x; acc.y += o.y;
        int col = c2 * 2;
        float bx = bias[col], by = bias[col + 1];
        float2 r = *reinterpret_cast<const float2*>(resid + (long)row * D_H + col);
        if (RELU) {
            t2.x = r.x + fmaxf(acc.x + bx, 0.0f);
            t2.y = r.y + fmaxf(acc.y + by, 0.0f);
        } else {
            t2.x = r.x + acc.x + bx;
            t2.y = r.y + acc.y + by;
        }
    }

    float s = t2.x + t2.y, sq = t2.x * t2.x + t2.y * t2.y;
#pragma unroll
    for (int o = 16; o; o >>= 1) {
        s  += __shfl_xor_sync(0xFFFFFFFFu, s, o);
        sq += __shfl_xor_sync(0xFFFFFFFFu, sq, o);
    }
    __shared__ float ss[8], ssq[8];
    int wid = tid >> 5;
    if ((tid & 31) == 0) { ss[wid] = s; ssq[wid] = sq; }
    __syncthreads();
    float ts = 0.f, tq = 0.f;
#pragma unroll
    for (int i = 0; i < 8; i++) { ts += ss[i]; tq += ssq[i]; }
    float mu  = ts * (1.0f / D_H);
    float var = tq * (1.0f / D_H) - mu * mu;

    if (par == 0) {
        float rstd = rsqrtf(var + LN_EPS);
        int col = c2 * 2;
        float2 o;
        o.x = (t2.x - mu) * rstd * gamma[col]     + beta[col];
        o.y = (t2.y - mu) * rstd * gamma[col + 1] + beta[col + 1];
        *reinterpret_cast<float2*>(out + (long)row * D_H + col) = o;
    }
}

// ---------------- launch ----------------
extern "C" void kernel_launch(void* const* d_in, const int* in_sizes, int n_in,
                              void* d_out, int out_size) {
    const float* x      = (const float*)d_in[0];
    const int*   ei     = (const int*)d_in[1];     // [2,E] int32
    const float* ew     = (const float*)d_in[2];
    const float* W1     = (const float*)d_in[3];
    const float* b1     = (const float*)d_in[4];
    const float* W2     = (const float*)d_in[5];
    const float* b2     = (const float*)d_in[6];
    const float* Wres   = (const float*)d_in[7];
    const float* bres   = (const float*)d_in[8];
    const float* gamma1 = (const float*)d_in[9];
    const float* beta1  = (const float*)d_in[10];
    const float* gamma2 = (const float*)d_in[11];
    const float* beta2  = (const float*)d_in[12];
    float* out = (float*)d_out;

    const int E = in_sizes[2];
    const int* src = ei;
    const int* dst = ei + E;

    __half *p_h1h = nullptr;
    float *p_hres = nullptr, *p_h = nullptr;
    cudaGetSymbolAddress((void**)&p_h1h,  g_h1h);
    cudaGetSymbolAddress((void**)&p_hres, g_hres);
    cudaGetSymbolAddress((void**)&p_h,    g_h);

    // lazily-created side stream + events (host resources only)
    static cudaStream_t sideStream = nullptr;
    static cudaEvent_t  evFork = nullptr, evJoin = nullptr;
    if (!sideStream) {
        if (cudaStreamCreateWithFlags(&sideStream, cudaStreamNonBlocking) != cudaSuccess)
            sideStream = nullptr;
        if (sideStream) {
            cudaEventCreateWithFlags(&evFork, cudaEventDisableTiming);
            cudaEventCreateWithFlags(&evJoin, cudaEventDisableTiming);
        }
    }
    cudaStream_t cs = sideStream ? sideStream : (cudaStream_t)0;

    // fork: CSR build chain on side stream (4 kernels)
    if (sideStream) {
        cudaEventRecord(evFork, 0);
        cudaStreamWaitEvent(sideStream, evFork, 0);
    }
    degcnt_kernel<<<(E + 255) / 256, 256, 0, cs>>>(dst, ew, E);
    scan1_kernel<<<NB_SCAN, 256, 0, cs>>>();
    scan2_kernel<<<NB_SCAN, 256, 0, cs>>>(E);
    fill_kernel<<<(E + 255) / 256, 256, 0, cs>>>(src, dst, ew, E);
    if (sideStream) cudaEventRecord(evJoin, sideStream);

    const int mblk = (N_NODES + 127) / 128;   // 157
    const int nb = D_H / 128;                 // 2 col-blocks per matrix

    // main stream (concurrent with CSR build):
    // h1(fp16) = x@W1 ; hres(fp32) = x@Wres + bres
    f16_gemm_kernel<D_IN><<<dim3(mblk, 2 * nb), 256>>>(
        x, N_NODES, nb,
        W1, nullptr, p_h1h, nullptr,
        Wres, bres, nullptr, p_hres);

    // join: gather needs both CSR and GEMM results
    if (sideStream) cudaStreamWaitEvent((cudaStream_t)0, evJoin, 0);

    // hop 0: gather(h1) + b1 + relu + hres residual + LN -> h (fp32)
    gather_ln_kernel<true><<<N_NODES, 256>>>(
        p_h1h, p_hres, b1, gamma1, beta1, p_h);

    // h2(fp16) = h @ W2
    f16_gemm_kernel<D_H><<<dim3(mblk, nb), 256>>>(
        p_h, N_NODES, nb,
        W2, nullptr, p_h1h, nullptr,
        W2, nullptr, p_h1h, nullptr);

    // hop 1: gather(h2) + b2 + h residual + LN -> out (fp32)
    gather_ln_kernel<false><<<N_NODES, 256>>>(
        p_h1h, p_h, b2, gamma2, beta2, out);
}

// round 16
// speedup vs baseline: 1.0839x; 1.0111x over previous
#include <cuda_runtime.h>
#include <cuda_fp16.h>
#include <stdint.h>

#define N_NODES 20000
#define D_IN    128
#define D_H     256
#define D_H2    128               // half2 columns
#define LN_EPS  1e-5f
#define MAX_E   330000
#define NB_SCAN ((N_NODES + 255) / 256)   // 79
#define DEG_SCALE 1048576.0f              // 2^20 fixed-point for edge weights
#define H_SPLIT 10112                     // 79 * 128, pipeline split row

// ---------------- scratch (no dynamic allocation allowed) ----------------
// invariant: g_degcnt == 0 at kernel_launch entry (zeroed statics; scan1
// restores after reading)
__device__ unsigned long long g_degcnt[N_NODES];  // cnt<<40 | deg_fp20
__device__ float  g_dinv[N_NODES];
__device__ int    g_off [N_NODES + 1];
__device__ int    g_cur [N_NODES];        // fill cursor (re-init by scan2)
__device__ int    g_blksum[NB_SCAN];
__device__ int2   g_csr [MAX_E];          // {src, nrm-as-int}
__device__ __half g_h1h [N_NODES * D_H];  // x@W1 (fp16) — read-only after GEMM1
__device__ __half g_h2h [N_NODES * D_H];  // h@W2 (fp16) — separate, no aliasing
__device__ float  g_hres[N_NODES * D_H];  // x@Wres + bres (fp32)
__device__ float  g_h   [N_NODES * D_H];  // after LN1 (fp32)

// ---------------- helpers ----------------
__device__ __forceinline__ uint32_t pack_h2(float a, float b) {
    __half2 h = __floats2half2_rn(a, b);
    return *reinterpret_cast<uint32_t*>(&h);
}

__device__ __forceinline__ void mma_f16(float* c, const uint32_t* a, const uint32_t* b) {
    asm volatile(
        "mma.sync.aligned.m16n8k16.row.col.f32.f16.f16.f32 "
        "{%0,%1,%2,%3}, {%4,%5,%6,%7}, {%8,%9}, {%0,%1,%2,%3};"
        : "+f"(c[0]), "+f"(c[1]), "+f"(c[2]), "+f"(c[3])
        : "r"(a[0]), "r"(a[1]), "r"(a[2]), "r"(a[3]), "r"(b[0]), "r"(b[1]));
}

// ---------------- degree + count via ONE packed 64-bit atomic ---------------
__global__ void degcnt_kernel(const int* __restrict__ dst,
                              const float* __restrict__ w, int E) {
    for (int e = blockIdx.x * blockDim.x + threadIdx.x; e < E;
         e += gridDim.x * blockDim.x) {
        int d = dst[e];
        unsigned long long packed =
            (1ULL << 40) | (unsigned long long)__float2uint_rn(w[e] * DEG_SCALE);
        atomicAdd(&g_degcnt[d], packed);
    }
}

// ---------------- scan pass 1: per-block exclusive scan + dinv --------------
__global__ void scan1_kernel() {
    const int t = threadIdx.x, b = blockIdx.x;
    const int i = b * 256 + t;
    const int lane = t & 31, wid = t >> 5;

    int v = 0;
    if (i < N_NODES) {
        unsigned long long pc = g_degcnt[i];
        g_degcnt[i] = 0ULL;                               // restore invariant
        v = (int)(pc >> 40);
        float d = (float)(pc & 0xFFFFFFFFFFULL) * (1.0f / DEG_SCALE);
        g_dinv[i] = rsqrtf(d + 1.0f);                     // + self-loop
    }

    int s = v;
#pragma unroll
    for (int o = 1; o < 32; o <<= 1) {
        int u = __shfl_up_sync(0xFFFFFFFFu, s, o);
        if (lane >= o) s += u;
    }
    __shared__ int wsum[8];
    if (lane == 31) wsum[wid] = s;
    __syncthreads();
    int base = 0;
#pragma unroll
    for (int w = 0; w < 8; w++) base += (w < wid) ? wsum[w] : 0;
    if (i < N_NODES) g_off[i] = base + s - v;
    if (t == 255) g_blksum[b] = base + s;
}

// ---------------- scan pass 2: add block bases, init fill cursor ------------
__global__ void scan2_kernel(int E) {
    const int t = threadIdx.x, b = blockIdx.x;
    __shared__ int sbase;
    if (t < 32) {
        int acc = 0;
        for (int j = t; j < b; j += 32) acc += g_blksum[j];
#pragma unroll
        for (int o = 16; o; o >>= 1) acc += __shfl_xor_sync(0xFFFFFFFFu, acc, o);
        if (t == 0) sbase = acc;
    }
    __syncthreads();
    const int i = b * 256 + t;
    if (i < N_NODES) {
        int off = g_off[i] + sbase;
        g_off[i] = off;
        g_cur[i] = off;
    }
    if (b == 0 && t == 0) g_off[N_NODES] = E;
}

// ---------------- CSR fill: ONE 8-byte store per edge ----------------
__global__ void fill_kernel(const int* __restrict__ src,
                            const int* __restrict__ dst,
                            const float* __restrict__ w, int E) {
    for (int e = blockIdx.x * blockDim.x + threadIdx.x; e < E;
         e += gridDim.x * blockDim.x) {
        int s = src[e];
        int d = dst[e];
        int pos = atomicAdd(&g_cur[d], 1);
        float nrm = g_dinv[s] * w[e] * g_dinv[d];
        g_csr[pos] = make_int2(s, __float_as_int(nrm));
    }
}

// ---------------- FP16 tensor-core GEMM (row-range [m0, M)) ----------------
// C[M,256] = A[M,K] @ B[K,256] (+bias). BM=128 BN=128 BK=16, 256 thr (8 warps).
template<int K>
__global__ __launch_bounds__(256)
void f16_gemm_kernel(const float* __restrict__ A, int m0, int M, int nb,
                     const float* __restrict__ Bm1, const float* __restrict__ bias1,
                     __half* __restrict__ C1h, float* __restrict__ C1f,
                     const float* __restrict__ Bm2, const float* __restrict__ bias2,
                     __half* __restrict__ C2h, float* __restrict__ C2f) {
    __shared__ uint32_t As2[128][12];
    __shared__ uint32_t Bs2[8][136];

    const int tid  = threadIdx.x;
    const int lane = tid & 31;
    const int wid  = tid >> 5;
    const int wm   = (wid & 1) * 64;
    const int wn   = (wid >> 1) * 32;
    const int g    = lane >> 2;
    const int tg   = lane & 3;

    const int bm  = m0 + blockIdx.x * 128;
    const int mat = blockIdx.y / nb;
    const int bn  = (blockIdx.y % nb) * 128;

    const float* Bw   = mat ? Bm2   : Bm1;
    const float* bias = mat ? bias2 : bias1;
    __half*      Ch   = mat ? C2h   : C1h;
    float*       Cf   = mat ? C2f   : C1f;

    const int a_row = tid >> 1;
    const int a_k   = (tid & 1) * 8;
    const int a_k2  = (tid & 1) * 4;
    const int b_r   = tid >> 5;
    const int b_c   = (tid & 31) * 4;
    const bool a_ok = (bm + a_row) < M;
    const long a_base = (long)(bm + a_row) * K;

    float acc[4][4][4];
#pragma unroll
    for (int mt = 0; mt < 4; mt++)
#pragma unroll
        for (int nt = 0; nt < 4; nt++)
#pragma unroll
            for (int i = 0; i < 4; i++) acc[mt][nt][i] = 0.0f;

    float4 av0 = make_float4(0.f,0.f,0.f,0.f), av1 = av0;
    if (a_ok) {
        av0 = *reinterpret_cast<const float4*>(A + a_base + a_k);
        av1 = *reinterpret_cast<const float4*>(A + a_base + a_k + 4);
    }
    float4 bv0 = *reinterpret_cast<const float4*>(Bw + (long)(2 * b_r)     * D_H + bn + b_c);
    float4 bv1 = *reinterpret_cast<const float4*>(Bw + (long)(2 * b_r + 1) * D_H + bn + b_c);

    const int T = K / 16;
    for (int t = 0; t < T; t++) {
        __syncthreads();
        {
            uint4 pa = make_uint4(pack_h2(av0.x, av0.y), pack_h2(av0.z, av0.w),
                                  pack_h2(av1.x, av1.y), pack_h2(av1.z, av1.w));
            *reinterpret_cast<uint4*>(&As2[a_row][a_k2]) = pa;
            uint4 pb = make_uint4(pack_h2(bv0.x, bv1.x), pack_h2(bv0.y, bv1.y),
                                  pack_h2(bv0.z, bv1.z), pack_h2(bv0.w, bv1.w));
            *reinterpret_cast<uint4*>(&Bs2[b_r][b_c]) = pb;
        }
        __syncthreads();

        if (t + 1 < T) {
            int kt = (t + 1) * 16;
            av0 = make_float4(0.f,0.f,0.f,0.f); av1 = av0;
            if (a_ok) {
                av0 = *reinterpret_cast<const float4*>(A + a_base + kt + a_k);
                av1 = *reinterpret_cast<const float4*>(A + a_base + kt + a_k + 4);
            }
            bv0 = *reinterpret_cast<const float4*>(Bw + (long)(kt + 2 * b_r)     * D_H + bn + b_c);
            bv1 = *reinterpret_cast<const float4*>(Bw + (long)(kt + 2 * b_r + 1) * D_H + bn + b_c);
        }

        uint32_t af[4][4], bf[4][2];
#pragma unroll
        for (int mt = 0; mt < 4; mt++) {
            int r0 = wm + mt * 16 + g;
            af[mt][0] = As2[r0    ][tg    ];
            af[mt][1] = As2[r0 + 8][tg    ];
            af[mt][2] = As2[r0    ][tg + 4];
            af[mt][3] = As2[r0 + 8][tg + 4];
        }
#pragma unroll
        for (int nt = 0; nt < 4; nt++) {
            int c0 = wn + nt * 8 + g;
            bf[nt][0] = Bs2[tg    ][c0];
            bf[nt][1] = Bs2[tg + 4][c0];
        }
#pragma unroll
        for (int mt = 0; mt < 4; mt++)
#pragma unroll
            for (int nt = 0; nt < 4; nt++)
                mma_f16(acc[mt][nt], af[mt], bf[nt]);
    }

#pragma unroll
    for (int mt = 0; mt < 4; mt++) {
        int row = bm + wm + mt * 16 + g;
#pragma unroll
        for (int nt = 0; nt < 4; nt++) {
            int col = bn + wn + nt * 8 + tg * 2;
            float b0 = bias ? bias[col]     : 0.0f;
            float b1 = bias ? bias[col + 1] : 0.0f;
            float v00 = acc[mt][nt][0] + b0, v01 = acc[mt][nt][1] + b1;
            float v10 = acc[mt][nt][2] + b0, v11 = acc[mt][nt][3] + b1;
            if (Ch) {
                if (row < M)
                    *reinterpret_cast<__half2*>(Ch + (long)row * D_H + col) =
                        __floats2half2_rn(v00, v01);
                if (row + 8 < M)
                    *reinterpret_cast<__half2*>(Ch + (long)(row + 8) * D_H + col) =
                        __floats2half2_rn(v10, v11);
            } else {
                if (row < M)
                    *reinterpret_cast<float2*>(Cf + (long)row * D_H + col) =
                        make_float2(v00, v01);
                if (row + 8 < M)
                    *reinterpret_cast<float2*>(Cf + (long)(row + 8) * D_H + col) =
                        make_float2(v10, v11);
            }
        }
    }
}

// ---------------- fused CSR gather (half2, split-edge) + ReLU? + res + LN ---
// processes rows [row0, row0+gridDim.x)
template<bool RELU>
__global__ __launch_bounds__(256)
void gather_ln_kernel(int row0,
                      const __half* __restrict__ feat,
                      const float* __restrict__ resid,
                      const float* __restrict__ bias,
                      const float* __restrict__ gamma,
                      const float* __restrict__ beta,
                      float* __restrict__ out) {
    const int row = row0 + blockIdx.x;
    const int tid = threadIdx.x;
    const int c2  = tid & 127;
    const int par = tid >> 7;
    const __half2* f2 = reinterpret_cast<const __half2*>(feat);
    const long idx2 = (long)row * D_H2 + c2;

    __shared__ int2   s_meta[64];
    __shared__ float2 s_par[128];

    const int beg = g_off[row];
    const int end = g_off[row + 1];
    const float di = g_dinv[row];

    float2 a0 = make_float2(0.f, 0.f), a1 = a0, a2 = a0, a3 = a0;
    if (par == 0) {   // self-loop
        float2 v = __half22float2(f2[idx2]);
        a0.x = di * di * v.x;
        a0.y = di * di * v.y;
    }

    for (int chunk = beg; chunk < end; chunk += 64) {
        int n = min(64, end - chunk);
        if (chunk != beg) __syncthreads();
        if (tid < n) s_meta[tid] = g_csr[chunk + tid];
        __syncthreads();
        int k = par;
        for (; k + 6 < n; k += 8) {
            int2 m0 = s_meta[k], m1 = s_meta[k + 2], m2 = s_meta[k + 4], m3 = s_meta[k + 6];
            float2 v0 = __half22float2(f2[(long)m0.x * D_H2 + c2]);
            float2 v1 = __half22float2(f2[(long)m1.x * D_H2 + c2]);
            float2 v2 = __half22float2(f2[(long)m2.x * D_H2 + c2]);
            float2 v3 = __half22float2(f2[(long)m3.x * D_H2 + c2]);
            float n0 = __int_as_float(m0.y), n1 = __int_as_float(m1.y);
            float n2 = __int_as_float(m2.y), n3 = __int_as_float(m3.y);
            a0.x += n0 * v0.x; a0.y += n0 * v0.y;
            a1.x += n1 * v1.x; a1.y += n1 * v1.y;
            a2.x += n2 * v2.x; a2.y += n2 * v2.y;
            a3.x += n3 * v3.x; a3.y += n3 * v3.y;
        }
        for (; k < n; k += 2) {
            int2 m = s_meta[k];
            float2 v = __half22float2(f2[(long)m.x * D_H2 + c2]);
            float nn = __int_as_float(m.y);
            a0.x += nn * v.x; a0.y += nn * v.y;
        }
    }

    float2 acc = make_float2((a0.x + a1.x) + (a2.x + a3.x),
                             (a0.y + a1.y) + (a2.y + a3.y));

    __syncthreads();
    if (par == 1) s_par[c2] = acc;
    __syncthreads();

    float2 t2 = make_float2(0.f, 0.f);
    if (par == 0) {
        float2 o = s_par[c2];
        acc.x += o.x; acc.y += o.y;
        int col = c2 * 2;
        float bx = bias[col], by = bias[col + 1];
        float2 r = *reinterpret_cast<const float2*>(resid + (long)row * D_H + col);
        if (RELU) {
            t2.x = r.x + fmaxf(acc.x + bx, 0.0f);
            t2.y = r.y + fmaxf(acc.y + by, 0.0f);
        } else {
            t2.x = r.x + acc.x + bx;
            t2.y = r.y + acc.y + by;
        }
    }

    float s = t2.x + t2.y, sq = t2.x * t2.x + t2.y * t2.y;
#pragma unroll
    for (int o = 16; o; o >>= 1) {
        s  += __shfl_xor_sync(0xFFFFFFFFu, s, o);
        sq += __shfl_xor_sync(0xFFFFFFFFu, sq, o);
    }
    __shared__ float ss[8], ssq[8];
    int wid = tid >> 5;
    if ((tid & 31) == 0) { ss[wid] = s; ssq[wid] = sq; }
    __syncthreads();
    float ts = 0.f, tq = 0.f;
#pragma unroll
    for (int i = 0; i < 8; i++) { ts += ss[i]; tq += ssq[i]; }
    float mu  = ts * (1.0f / D_H);
    float var = tq * (1.0f / D_H) - mu * mu;

    if (par == 0) {
        float rstd = rsqrtf(var + LN_EPS);
        int col = c2 * 2;
        float2 o;
        o.x = (t2.x - mu) * rstd * gamma[col]     + beta[col];
        o.y = (t2.y - mu) * rstd * gamma[col + 1] + beta[col + 1];
        *reinterpret_cast<float2*>(out + (long)row * D_H + col) = o;
    }
}

// ---------------- launch ----------------
extern "C" void kernel_launch(void* const* d_in, const int* in_sizes, int n_in,
                              void* d_out, int out_size) {
    const float* x      = (const float*)d_in[0];
    const int*   ei     = (const int*)d_in[1];     // [2,E] int32
    const float* ew     = (const float*)d_in[2];
    const float* W1     = (const float*)d_in[3];
    const float* b1     = (const float*)d_in[4];
    const float* W2     = (const float*)d_in[5];
    const float* b2     = (const float*)d_in[6];
    const float* Wres   = (const float*)d_in[7];
    const float* bres   = (const float*)d_in[8];
    const float* gamma1 = (const float*)d_in[9];
    const float* beta1  = (const float*)d_in[10];
    const float* gamma2 = (const float*)d_in[11];
    const float* beta2  = (const float*)d_in[12];
    float* out = (float*)d_out;

    const int E = in_sizes[2];
    const int* src = ei;
    const int* dst = ei + E;

    __half *p_h1h = nullptr, *p_h2h = nullptr;
    float *p_hres = nullptr, *p_h = nullptr;
    cudaGetSymbolAddress((void**)&p_h1h,  g_h1h);
    cudaGetSymbolAddress((void**)&p_h2h,  g_h2h);
    cudaGetSymbolAddress((void**)&p_hres, g_hres);
    cudaGetSymbolAddress((void**)&p_h,    g_h);

    // lazily-created side stream + events (host resources only)
    static cudaStream_t sideStream = nullptr;
    static cudaEvent_t  evFork = nullptr, evJoin = nullptr, evA = nullptr, evB = nullptr;
    if (!sideStream) {
        if (cudaStreamCreateWithFlags(&sideStream, cudaStreamNonBlocking) != cudaSuccess)
            sideStream = nullptr;
        if (sideStream) {
            cudaEventCreateWithFlags(&evFork, cudaEventDisableTiming);
            cudaEventCreateWithFlags(&evJoin, cudaEventDisableTiming);
            cudaEventCreateWithFlags(&evA,    cudaEventDisableTiming);
            cudaEventCreateWithFlags(&evB,    cudaEventDisableTiming);
        }
    }
    cudaStream_t cs = sideStream ? sideStream : (cudaStream_t)0;

    // fork: CSR build chain on side stream (4 kernels)
    if (sideStream) {
        cudaEventRecord(evFork, 0);
        cudaStreamWaitEvent(sideStream, evFork, 0);
    }
    degcnt_kernel<<<(E + 255) / 256, 256, 0, cs>>>(dst, ew, E);
    scan1_kernel<<<NB_SCAN, 256, 0, cs>>>();
    scan2_kernel<<<NB_SCAN, 256, 0, cs>>>(E);
    fill_kernel<<<(E + 255) / 256, 256, 0, cs>>>(src, dst, ew, E);
    if (sideStream) cudaEventRecord(evJoin, sideStream);

    const int nb = D_H / 128;                    // 2 col-blocks per matrix
    const int mblk_all = (N_NODES + 127) / 128;  // 157
    const int mblk_a   = H_SPLIT / 128;          // 79
    const int mblk_b   = (N_NODES - H_SPLIT + 127) / 128;  // 78

    // main stream (concurrent with CSR build):
    // h1(fp16) = x@W1 ; hres(fp32) = x@Wres + bres
    f16_gemm_kernel<D_IN><<<dim3(mblk_all, 2 * nb), 256>>>(
        x, 0, N_NODES, nb,
        W1, nullptr, p_h1h, nullptr,
        Wres, bres, nullptr, p_hres);

    // join: gather needs both CSR and GEMM results
    if (sideStream) cudaStreamWaitEvent((cudaStream_t)0, evJoin, 0);

    if (sideStream) {
        // pipelined middle: gather1_A -> {GEMM2_A || gather1_B} -> GEMM2_B
        // h2 goes to g_h2h (separate from g_h1h, which gather1_B still reads)
        gather_ln_kernel<true><<<H_SPLIT, 256>>>(
            0, p_h1h, p_hres, b1, gamma1, beta1, p_h);
        cudaEventRecord(evA, 0);
        cudaStreamWaitEvent(sideStream, evA, 0);
        gather_ln_kernel<true><<<N_NODES - H_SPLIT, 256, 0, sideStream>>>(
            H_SPLIT, p_h1h, p_hres, b1, gamma1, beta1, p_h);
        cudaEventRecord(evB, sideStream);

        f16_gemm_kernel<D_H><<<dim3(mblk_a, nb), 256>>>(
            p_h, 0, H_SPLIT, nb,
            W2, nullptr, p_h2h, nullptr,
            W2, nullptr, p_h2h, nullptr);
        cudaStreamWaitEvent((cudaStream_t)0, evB, 0);
        f16_gemm_kernel<D_H><<<dim3(mblk_b, nb), 256>>>(
            p_h, H_SPLIT, N_NODES, nb,
            W2, nullptr, p_h2h, nullptr,
            W2, nullptr, p_h2h, nullptr);
    } else {
        // serial fallback
        gather_ln_kernel<true><<<N_NODES, 256>>>(
            0, p_h1h, p_hres, b1, gamma1, beta1, p_h);
        f16_gemm_kernel<D_H><<<dim3(mblk_all, nb), 256>>>(
            p_h, 0, N_NODES, nb,
            W2, nullptr, p_h2h, nullptr,
            W2, nullptr, p_h2h, nullptr);
    }

    // hop 1: gather(h2) + b2 + h residual + LN -> out (fp32)
    gather_ln_kernel<false><<<N_NODES, 256>>>(
        0, p_h2h, p_h, b2, gamma2, beta2, out);
}